// round 5
// baseline (speedup 1.0000x reference)
#include <cuda_runtime.h>
#include <math.h>

#define BB 2
#define CC 128
#define LL 56
#define PL 3136      // 56*56
#define SP 175616    // 56^3
#define SLEN 512     // 8*8*8 pooled spatial

// Scratch (static device globals; no allocation)
__device__ __align__(16) float g_sax0[BB][CC][LL];     // d-axis means
__device__ __align__(16) float g_shp[BB * CC][4][LL];  // h-axis partial sums
__device__ __align__(16) float g_swp[BB * CC][4][LL];  // w-axis partial sums
__device__ __align__(16) float g_gate[3][BB][CC][LL];  // sigmoid gates
__device__ __align__(16) float g_y[BB][CC][SLEN];      // pooled tensor
__device__ double g_part[BB * CC * 8][2];              // per-K3-block (sum,sumsq)
__device__ float g_ca[BB][CC];                         // channel attention

__device__ __forceinline__ float hsum4(float4 v) {
    return (v.x + v.y) + (v.z + v.w);
}

// ---------------------------------------------------------------------------
// K1: axis-mean partials, all-float4. grid = bc*4+chunk (1024), blockDim 416
// (active t<392). Thread: q = t%14 (float4 col), R0 = t/14 -> rows R0, R0+28.
// ---------------------------------------------------------------------------
__global__ void k1_axis_means(const float* __restrict__ x) {
    int id = blockIdx.x;
    int chunk = id & 3;
    int bc = id >> 2;
    const float4* xp = reinterpret_cast<const float4*>(x + (size_t)bc * SP)
                     + (size_t)chunk * 14 * 784;

    __shared__ float sdp[13][14];     // warp x d plane partials
    __shared__ float shq[56][14];     // per-(h,q) sums
    __shared__ float4 swq[28][14];    // per-(R0,q) float4 sums

    int t = threadIdx.x;
    bool act = t < 392;
    int q = t % 14, R0 = t / 14;      // R0 0..27 for active
    int wid = t >> 5, lane = t & 31;

    float4 ah1 = {0, 0, 0, 0}, ah2 = {0, 0, 0, 0}, aw = {0, 0, 0, 0};

#pragma unroll
    for (int d = 0; d < 14; ++d) {
        float4 v1 = {0, 0, 0, 0}, v2 = {0, 0, 0, 0};
        if (act) {
            v1 = xp[d * 784 + R0 * 14 + q];
            v2 = xp[d * 784 + (R0 + 28) * 14 + q];
        }
        ah1.x += v1.x; ah1.y += v1.y; ah1.z += v1.z; ah1.w += v1.w;
        ah2.x += v2.x; ah2.y += v2.y; ah2.z += v2.z; ah2.w += v2.w;
        aw.x += v1.x + v2.x; aw.y += v1.y + v2.y;
        aw.z += v1.z + v2.z; aw.w += v1.w + v2.w;
        float qs = hsum4(v1) + hsum4(v2);
#pragma unroll
        for (int o = 16; o; o >>= 1) qs += __shfl_down_sync(0xffffffffu, qs, o);
        if (lane == 0) sdp[wid][d] = qs;
    }
    if (act) {
        shq[R0][q] = hsum4(ah1);
        shq[R0 + 28][q] = hsum4(ah2);
        swq[R0][q] = aw;
    }
    __syncthreads();

    int b = bc >> 7, c = bc & 127;
    if (t < 14) {
        float s = 0.f;
#pragma unroll
        for (int w = 0; w < 13; ++w) s += sdp[w][t];
        g_sax0[b][c][chunk * 14 + t] = s * (1.0f / (float)PL);
    } else if (t >= 64 && t < 64 + LL) {
        int h = t - 64;
        float s = 0.f;
#pragma unroll
        for (int j = 0; j < 14; ++j) s += shq[h][j];
        g_shp[bc][chunk][h] = s;
    } else if (t >= 128 && t < 128 + LL) {
        int w = t - 128;
        int qq = w >> 2, comp = w & 3;
        float s = 0.f;
#pragma unroll
        for (int r = 0; r < 28; ++r) {
            const float* p = reinterpret_cast<const float*>(&swq[r][qq]);
            s += p[comp];
        }
        g_swp[bc][chunk][w] = s;
    }
}

// ---------------------------------------------------------------------------
// K2: combine partials + depthwise conv + GroupNorm(4) + sigmoid.
// Launched twice: grid 16 (axes 0,1) and grid 8 (axis 2, axis_base=2).
// ---------------------------------------------------------------------------
__global__ void k2_gates(int axis_base,
                         const float* __restrict__ wl, const float* __restrict__ bl,
                         const float* __restrict__ ws, const float* __restrict__ bs,
                         const float* __restrict__ wm, const float* __restrict__ bm,
                         const float* __restrict__ wg, const float* __restrict__ bg,
                         const float* __restrict__ gd, const float* __restrict__ btd,
                         const float* __restrict__ gh, const float* __restrict__ bth,
                         const float* __restrict__ gw, const float* __restrict__ btw) {
    int idx = blockIdx.x;
    int axis = axis_base + (idx >> 3);
    int b = (idx >> 2) & 1;
    int g = idx & 3;
    const int ksz[4] = {3, 5, 7, 9};
    const float* wptr[4] = {wl, ws, wm, wg};
    const float* bptr[4] = {bl, bs, bm, bg};
    const float* gam[3] = {gd, gh, gw};
    const float* bet[3] = {btd, bth, btw};
    int k = ksz[g], half = k >> 1;

    __shared__ float s_in[32][LL];
    __shared__ float s_out[32][LL];
    __shared__ float s_w[32 * 9];
    __shared__ float s_b[32];
    __shared__ float red[2];
    __shared__ float rs[8], rq[8];

    int tid = threadIdx.x;
    for (int i = tid; i < 32 * LL; i += 256) {
        int cc = i / LL, l = i % LL;
        int c = g * 32 + cc;
        float v;
        if (axis == 0) {
            v = g_sax0[b][c][l];
        } else {
            int bcc = b * 128 + c;
            const float(*pp)[4][LL] = (axis == 1) ? g_shp : g_swp;
            v = (pp[bcc][0][l] + pp[bcc][1][l] + pp[bcc][2][l] + pp[bcc][3][l])
                * (1.0f / (float)PL);
        }
        s_in[cc][l] = v;
    }
    for (int i = tid; i < 32 * k; i += 256) s_w[i] = wptr[g][i];
    if (tid < 32) s_b[tid] = bptr[g][tid];
    __syncthreads();

    float lsum = 0.f, lsq = 0.f;
    for (int i = tid; i < 32 * LL; i += 256) {
        int cc = i / LL, l = i % LL;
        float acc = s_b[cc];
        for (int j = 0; j < k; ++j) {
            int p = l + j - half;
            if (p >= 0 && p < LL) acc += s_w[cc * k + j] * s_in[cc][p];
        }
        s_out[cc][l] = acc;
        lsum += acc;
        lsq += acc * acc;
    }
#pragma unroll
    for (int o = 16; o; o >>= 1) {
        lsum += __shfl_down_sync(0xffffffffu, lsum, o);
        lsq  += __shfl_down_sync(0xffffffffu, lsq, o);
    }
    if ((tid & 31) == 0) { rs[tid >> 5] = lsum; rq[tid >> 5] = lsq; }
    __syncthreads();
    if (tid == 0) {
        float S = 0.f, Q = 0.f;
        for (int i = 0; i < 8; ++i) { S += rs[i]; Q += rq[i]; }
        float n = 32.f * LL;
        float mu = S / n;
        float var = Q / n - mu * mu;
        red[0] = mu;
        red[1] = rsqrtf(var + 1e-5f);
    }
    __syncthreads();
    float mu = red[0], rstd = red[1];
    for (int i = tid; i < 32 * LL; i += 256) {
        int cc = i / LL, l = i % LL;
        int c = g * 32 + cc;
        float v = (s_out[cc][l] - mu) * rstd * gam[axis][c] + bet[axis][c];
        g_gate[axis][b][c][l] = 1.f / (1.f + expf(-v));
    }
}

// ---------------------------------------------------------------------------
// K3: pool gated x into y, all-float4, REVERSE block order (L2 seam reuse
// with K1's tail). grid = 2048, blockDim 416.
// ---------------------------------------------------------------------------
__global__ void k3_pool(const float* __restrict__ x) {
    int id = (int)gridDim.x - 1 - (int)blockIdx.x;   // serpentine: reverse
    int dd = id & 7;
    int bc = id >> 3;
    int b = bc >> 7, c = bc & 127;
    const float4* xp = reinterpret_cast<const float4*>(x + (size_t)bc * SP)
                     + (size_t)dd * 7 * 784;

    __shared__ float sgd[7], sgh[LL], sgw[LL];
    __shared__ float4 sacc[56][14];
    __shared__ double pr[2][2];

    int t = threadIdx.x;
    bool act = t < 392;
    int q = t % 14, R0 = t / 14;

    if (t < LL) { sgh[t] = g_gate[1][b][c][t]; sgw[t] = g_gate[2][b][c][t]; }
    if (t >= 64 && t < 71) sgd[t - 64] = g_gate[0][b][c][dd * 7 + (t - 64)];
    __syncthreads();

    float4 a1 = {0, 0, 0, 0}, a2 = {0, 0, 0, 0};
    if (act) {
#pragma unroll
        for (int i = 0; i < 7; ++i) {
            float g = sgd[i];
            float4 v1 = xp[i * 784 + R0 * 14 + q];
            float4 v2 = xp[i * 784 + (R0 + 28) * 14 + q];
            a1.x += g * v1.x; a1.y += g * v1.y; a1.z += g * v1.z; a1.w += g * v1.w;
            a2.x += g * v2.x; a2.y += g * v2.y; a2.z += g * v2.z; a2.w += g * v2.w;
        }
        sacc[R0][q] = a1;
        sacc[R0 + 28][q] = a2;
    }
    __syncthreads();

    if (t < 64) {
        int hh = t >> 3, ww = t & 7;
        float s = 0.f;
#pragma unroll
        for (int ih = 0; ih < 7; ++ih) {
            int h = hh * 7 + ih;
            float inner = 0.f;
#pragma unroll
            for (int iw = 0; iw < 7; ++iw) {
                int w = ww * 7 + iw;
                const float* p = reinterpret_cast<const float*>(&sacc[h][w >> 2]);
                inner += p[w & 3] * sgw[w];
            }
            s += inner * sgh[h];
        }
        float yv = s * (1.0f / 343.0f);
        g_y[b][c][dd * 64 + hh * 8 + ww] = yv;
        double sv = yv, sq = (double)yv * yv;
#pragma unroll
        for (int o = 16; o; o >>= 1) {
            sv += __shfl_down_sync(0xffffffffu, sv, o);
            sq += __shfl_down_sync(0xffffffffu, sq, o);
        }
        if ((t & 31) == 0) { pr[t >> 5][0] = sv; pr[t >> 5][1] = sq; }
    }
    __syncthreads();
    if (t == 0) {
        g_part[id][0] = pr[0][0] + pr[1][0];
        g_part[id][1] = pr[0][1] + pr[1][1];
    }
}

// ---------------------------------------------------------------------------
// K4: stats + Gram + channel attention, merged. grid=16 (b,head), 256 threads.
// ---------------------------------------------------------------------------
__global__ void k4_attn(const float* __restrict__ gn, const float* __restrict__ btn,
                        const float* __restrict__ wq, const float* __restrict__ wk,
                        const float* __restrict__ wv) {
    int b = blockIdx.x >> 3;
    int head = blockIdx.x & 7;
    int c0 = head * 16;
    int tid = threadIdx.x;
    __shared__ float yy[16][516];   // padded to kill bank conflicts
    __shared__ double rs[8], rq[8];
    __shared__ float stat[2];
    __shared__ float Syy[16][16];
    __shared__ float Sy[16];

    {
        const float4* src = reinterpret_cast<const float4*>(&g_y[b][c0][0]);
        for (int i = tid; i < 16 * 128; i += 256) {
            int row = i >> 7, s4 = i & 127;
            float4 v = src[row * 128 + s4];
            float* dst = &yy[row][s4 * 4];
            dst[0] = v.x; dst[1] = v.y; dst[2] = v.z; dst[3] = v.w;
        }
    }

    double s = 0.0, q = 0.0;
    for (int i = tid; i < 1024; i += 256) {
        s += g_part[b * 1024 + i][0];
        q += g_part[b * 1024 + i][1];
    }
#pragma unroll
    for (int o = 16; o; o >>= 1) {
        s += __shfl_down_sync(0xffffffffu, s, o);
        q += __shfl_down_sync(0xffffffffu, q, o);
    }
    if ((tid & 31) == 0) { rs[tid >> 5] = s; rq[tid >> 5] = q; }
    __syncthreads();

    {
        int i = tid >> 4, j = tid & 15;
        const float4* ri = reinterpret_cast<const float4*>(&yy[i][0]);
        const float4* rj = reinterpret_cast<const float4*>(&yy[j][0]);
        float a0 = 0.f, a1 = 0.f, a2 = 0.f, a3 = 0.f;
#pragma unroll 4
        for (int s4 = 0; s4 < 128; ++s4) {
            float4 u = ri[s4], w = rj[s4];
            a0 += u.x * w.x; a1 += u.y * w.y;
            a2 += u.z * w.z; a3 += u.w * w.w;
        }
        Syy[i][j] = (a0 + a1) + (a2 + a3);
    }
    if (tid < 16) {
        double a = 0.0;
#pragma unroll
        for (int dd = 0; dd < 8; ++dd) a += g_part[(b * 128 + c0 + tid) * 8 + dd][0];
        Sy[tid] = (float)a;
    }
    if (tid == 0) {
        double S = 0.0, Q = 0.0;
        for (int i = 0; i < 8; ++i) { S += rs[i]; Q += rq[i]; }
        double n = (double)(CC * SLEN);
        double mu = S / n;
        double var = Q / n - mu * mu;
        stat[0] = (float)mu;
        stat[1] = (float)(1.0 / sqrt(var + 1e-5));
    }
    __syncthreads();

    if (tid < 16) {
        double mu = stat[0], rstd = stat[1];
        int i = tid;
        double ai = rstd * (double)gn[c0 + i];
        double bi = (double)btn[c0 + i] - mu * ai;
        double qi = (double)wq[c0 + i] * 0.25;  // includes HD^-0.5
        double sc_[16], vm[16];
        double m = -1e300;
#pragma unroll
        for (int j = 0; j < 16; ++j) {
            double aj = rstd * (double)gn[c0 + j];
            double bj = (double)btn[c0 + j] - mu * aj;
            double G = ai * aj * (double)Syy[i][j] + ai * bj * (double)Sy[i]
                     + bi * aj * (double)Sy[j] + 512.0 * bi * bj;
            sc_[j] = qi * (double)wk[c0 + j] * G;
            vm[j] = (double)wv[c0 + j] * (aj * (double)Sy[j] + 512.0 * bj) * (1.0 / 512.0);
            if (sc_[j] > m) m = sc_[j];
        }
        double sum = 0.0, o = 0.0;
#pragma unroll
        for (int j = 0; j < 16; ++j) {
            double e = exp(sc_[j] - m);
            sum += e;
            o += e * vm[j];
        }
        o /= sum;
        g_ca[b][c0 + i] = (float)(1.0 / (1.0 + exp(-o)));
    }
}

// ---------------------------------------------------------------------------
// K5: out = x * gd*gh*gw*ca. grid = 2048 FORWARD (hits K3's reverse-read tail
// in L2). Streaming loads (__ldcs, last use of x) + streaming stores (__stcs,
// out never re-read — don't evict x).
// ---------------------------------------------------------------------------
__global__ void k5_gate_out(const float* __restrict__ x, float* __restrict__ out) {
    int id = blockIdx.x;
    int ch = id & 7;
    int bc = id >> 3;
    int b = bc >> 7, c = bc & 127;
    const float4* xp = reinterpret_cast<const float4*>(x + (size_t)bc * SP);
    float4* op = reinterpret_cast<float4*>(out + (size_t)bc * SP);

    __shared__ float srs[392];
    __shared__ float4 sgw4[14];

    int t = threadIdx.x;
    bool act = t < 392;
    if (act) {
        int dl = t / 56, h = t % 56;
        srs[t] = g_gate[0][b][c][ch * 7 + dl] * g_gate[1][b][c][h] * g_ca[b][c];
    }
    if (t < 14) {
        sgw4[t] = reinterpret_cast<const float4*>(&g_gate[2][b][c][0])[t];
    }
    __syncthreads();

    if (act) {
        int q = t % 14, R0 = t / 14;
        float4 gw = sgw4[q];
        int base = ch * 5488 + R0 * 14 + q;
#pragma unroll
        for (int m = 0; m < 14; ++m) {
            float sc = srs[R0 + 28 * m];
            float4 v = __ldcs(&xp[base + m * 392]);
            v.x *= sc * gw.x;
            v.y *= sc * gw.y;
            v.z *= sc * gw.z;
            v.w *= sc * gw.w;
            __stcs(&op[base + m * 392], v);
        }
    }
}

// ---------------------------------------------------------------------------
extern "C" void kernel_launch(void* const* d_in, const int* in_sizes, int n_in,
                              void* d_out, int out_size) {
    const float* x = (const float*)d_in[0];
    float* out = (float*)d_out;

#define GATE_ARGS \
    (const float*)d_in[1], (const float*)d_in[2],   \
    (const float*)d_in[3], (const float*)d_in[4],   \
    (const float*)d_in[5], (const float*)d_in[6],   \
    (const float*)d_in[7], (const float*)d_in[8],   \
    (const float*)d_in[9], (const float*)d_in[10],  \
    (const float*)d_in[11], (const float*)d_in[12], \
    (const float*)d_in[13], (const float*)d_in[14]

    k1_axis_means<<<BB * CC * 4, 416>>>(x);
    k2_gates<<<16, 256>>>(0, GATE_ARGS);   // axes d, h
    k2_gates<<<8, 256>>>(2, GATE_ARGS);    // axis w
    k3_pool<<<BB * CC * 8, 416>>>(x);      // 4th launch -> profiled by ncu
    k4_attn<<<BB * 8, 256>>>(
        (const float*)d_in[15], (const float*)d_in[16],
        (const float*)d_in[17], (const float*)d_in[18],
        (const float*)d_in[19]);
    k5_gate_out<<<BB * CC * 8, 416>>>(x, out);
#undef GATE_ARGS
}

// round 6
// speedup vs baseline: 1.2585x; 1.2585x over previous
#include <cuda_runtime.h>
#include <math.h>

#define BB 2
#define CC 128
#define LL 56
#define PL 3136      // 56*56
#define SP 175616    // 56^3
#define SLEN 512     // 8*8*8 pooled spatial

// Scratch (static device globals; no allocation)
__device__ __align__(16) float g_sax0[BB][CC][LL];     // d-axis means (complete)
__device__ __align__(16) float g_shp[BB * CC][8][LL];  // h-axis partials (8 chunks)
__device__ __align__(16) float g_swp[BB * CC][8][LL];  // w-axis partials (8 chunks)
__device__ __align__(16) float g_gate[3][BB][CC][LL];  // sigmoid gates
__device__ __align__(16) float g_y[BB][CC][SLEN];      // pooled tensor
__device__ double g_part[BB * CC * 8][2];              // per-K3-block (sum,sumsq)
__device__ float g_ca[BB][CC];                         // channel attention

__device__ __forceinline__ float hsum4(float4 v) {
    return (v.x + v.y) + (v.z + v.w);
}

// ---------------------------------------------------------------------------
// K1: axis-mean partials, batched-MLP float4. grid = bc*8+dd (2048 blocks),
// blockDim 416 (active t<392). Thread (q=t%14, R0=t/14) covers rows R0, R0+28
// across 7 d-planes. Loads batched 7-deep; all reductions after the loads.
// ---------------------------------------------------------------------------
__global__ void __launch_bounds__(416, 2) k1_axis_means(const float* __restrict__ x) {
    int id = blockIdx.x;
    int dd = id & 7;
    int bc = id >> 3;
    const float4* xp = reinterpret_cast<const float4*>(x + (size_t)bc * SP)
                     + (size_t)dd * 7 * 784;

    __shared__ float sdp[13][7];      // warp x local-d plane partials
    __shared__ float shq[56][14];     // per-(h,q) sums
    __shared__ float4 swq[28][14];    // per-(R0,q) float4 sums

    int t = threadIdx.x;
    bool act = t < 392;
    int q = t % 14, R0 = t / 14;
    int wid = t >> 5, lane = t & 31;

    float pd[7];
    float4 ah1 = {0, 0, 0, 0}, ah2 = {0, 0, 0, 0}, aw = {0, 0, 0, 0};
    float4 v[7];

    // batch 1: row R0 across 7 planes
#pragma unroll
    for (int i = 0; i < 7; ++i) {
        float4 z = {0, 0, 0, 0};
        v[i] = act ? xp[i * 784 + R0 * 14 + q] : z;
    }
#pragma unroll
    for (int i = 0; i < 7; ++i) {
        pd[i] = hsum4(v[i]);
        ah1.x += v[i].x; ah1.y += v[i].y; ah1.z += v[i].z; ah1.w += v[i].w;
        aw.x += v[i].x; aw.y += v[i].y; aw.z += v[i].z; aw.w += v[i].w;
    }
    // batch 2: row R0+28 across 7 planes
#pragma unroll
    for (int i = 0; i < 7; ++i) {
        float4 z = {0, 0, 0, 0};
        v[i] = act ? xp[i * 784 + (R0 + 28) * 14 + q] : z;
    }
#pragma unroll
    for (int i = 0; i < 7; ++i) {
        pd[i] += hsum4(v[i]);
        ah2.x += v[i].x; ah2.y += v[i].y; ah2.z += v[i].z; ah2.w += v[i].w;
        aw.x += v[i].x; aw.y += v[i].y; aw.z += v[i].z; aw.w += v[i].w;
    }

    // plane-sum shuffle reductions (after all loads issued)
#pragma unroll
    for (int i = 0; i < 7; ++i) {
        float s = pd[i];
#pragma unroll
        for (int o = 16; o; o >>= 1) s += __shfl_down_sync(0xffffffffu, s, o);
        if (lane == 0) sdp[wid][i] = s;
    }
    if (act) {
        shq[R0][q] = hsum4(ah1);
        shq[R0 + 28][q] = hsum4(ah2);
        swq[R0][q] = aw;
    }
    __syncthreads();

    int b = bc >> 7, c = bc & 127;
    if (t < 7) {
        float s = 0.f;
#pragma unroll
        for (int w = 0; w < 13; ++w) s += sdp[w][t];
        g_sax0[b][c][dd * 7 + t] = s * (1.0f / (float)PL);
    } else if (t >= 64 && t < 64 + LL) {
        int h = t - 64;
        float s = 0.f;
#pragma unroll
        for (int j = 0; j < 14; ++j) s += shq[h][j];
        g_shp[bc][dd][h] = s;
    } else if (t >= 128 && t < 128 + LL) {
        int w = t - 128;
        int qq = w >> 2, comp = w & 3;
        float s = 0.f;
#pragma unroll
        for (int r = 0; r < 28; ++r) {
            const float* p = reinterpret_cast<const float*>(&swq[r][qq]);
            s += p[comp];
        }
        g_swp[bc][dd][w] = s;
    }
}

// ---------------------------------------------------------------------------
// K2: combine partials + depthwise conv + GroupNorm(4) + sigmoid.
// Launched twice: grid 16 (axes 0,1) and grid 8 (axis 2, axis_base=2).
// ---------------------------------------------------------------------------
__global__ void k2_gates(int axis_base,
                         const float* __restrict__ wl, const float* __restrict__ bl,
                         const float* __restrict__ ws, const float* __restrict__ bs,
                         const float* __restrict__ wm, const float* __restrict__ bm,
                         const float* __restrict__ wg, const float* __restrict__ bg,
                         const float* __restrict__ gd, const float* __restrict__ btd,
                         const float* __restrict__ gh, const float* __restrict__ bth,
                         const float* __restrict__ gw, const float* __restrict__ btw) {
    int idx = blockIdx.x;
    int axis = axis_base + (idx >> 3);
    int b = (idx >> 2) & 1;
    int g = idx & 3;
    const int ksz[4] = {3, 5, 7, 9};
    const float* wptr[4] = {wl, ws, wm, wg};
    const float* bptr[4] = {bl, bs, bm, bg};
    const float* gam[3] = {gd, gh, gw};
    const float* bet[3] = {btd, bth, btw};
    int k = ksz[g], half = k >> 1;

    __shared__ float s_in[32][LL];
    __shared__ float s_out[32][LL];
    __shared__ float s_w[32 * 9];
    __shared__ float s_b[32];
    __shared__ float red[2];
    __shared__ float rs[8], rq[8];

    int tid = threadIdx.x;
    for (int i = tid; i < 32 * LL; i += 256) {
        int cc = i / LL, l = i % LL;
        int c = g * 32 + cc;
        float v;
        if (axis == 0) {
            v = g_sax0[b][c][l];
        } else {
            int bcc = b * 128 + c;
            const float(*pp)[8][LL] = (axis == 1) ? g_shp : g_swp;
            float s = 0.f;
#pragma unroll
            for (int p = 0; p < 8; ++p) s += pp[bcc][p][l];
            v = s * (1.0f / (float)PL);
        }
        s_in[cc][l] = v;
    }
    for (int i = tid; i < 32 * k; i += 256) s_w[i] = wptr[g][i];
    if (tid < 32) s_b[tid] = bptr[g][tid];
    __syncthreads();

    float lsum = 0.f, lsq = 0.f;
    for (int i = tid; i < 32 * LL; i += 256) {
        int cc = i / LL, l = i % LL;
        float acc = s_b[cc];
        for (int j = 0; j < k; ++j) {
            int p = l + j - half;
            if (p >= 0 && p < LL) acc += s_w[cc * k + j] * s_in[cc][p];
        }
        s_out[cc][l] = acc;
        lsum += acc;
        lsq += acc * acc;
    }
#pragma unroll
    for (int o = 16; o; o >>= 1) {
        lsum += __shfl_down_sync(0xffffffffu, lsum, o);
        lsq  += __shfl_down_sync(0xffffffffu, lsq, o);
    }
    if ((tid & 31) == 0) { rs[tid >> 5] = lsum; rq[tid >> 5] = lsq; }
    __syncthreads();
    if (tid == 0) {
        float S = 0.f, Q = 0.f;
        for (int i = 0; i < 8; ++i) { S += rs[i]; Q += rq[i]; }
        float n = 32.f * LL;
        float mu = S / n;
        float var = Q / n - mu * mu;
        red[0] = mu;
        red[1] = rsqrtf(var + 1e-5f);
    }
    __syncthreads();
    float mu = red[0], rstd = red[1];
    for (int i = tid; i < 32 * LL; i += 256) {
        int cc = i / LL, l = i % LL;
        int c = g * 32 + cc;
        float v = (s_out[cc][l] - mu) * rstd * gam[axis][c] + bet[axis][c];
        g_gate[axis][b][c][l] = 1.f / (1.f + expf(-v));
    }
}

// ---------------------------------------------------------------------------
// K3: pool gated x into y, batched-MLP float4. grid = bc*8+dd (2048),
// blockDim 416. Forward block order (serpentine reverted).
// ---------------------------------------------------------------------------
__global__ void __launch_bounds__(416, 2) k3_pool(const float* __restrict__ x) {
    int id = blockIdx.x;
    int dd = id & 7;
    int bc = id >> 3;
    int b = bc >> 7, c = bc & 127;
    const float4* xp = reinterpret_cast<const float4*>(x + (size_t)bc * SP)
                     + (size_t)dd * 7 * 784;

    __shared__ float sgd[7], sgh[LL], sgw[LL];
    __shared__ float4 sacc[56][14];
    __shared__ double pr[2][2];

    int t = threadIdx.x;
    bool act = t < 392;
    int q = t % 14, R0 = t / 14;

    if (t < LL) { sgh[t] = g_gate[1][b][c][t]; sgw[t] = g_gate[2][b][c][t]; }
    if (t >= 64 && t < 71) sgd[t - 64] = g_gate[0][b][c][dd * 7 + (t - 64)];
    __syncthreads();

    if (act) {
        float4 v[7];
        float4 a1 = {0, 0, 0, 0}, a2 = {0, 0, 0, 0};
#pragma unroll
        for (int i = 0; i < 7; ++i) v[i] = xp[i * 784 + R0 * 14 + q];
#pragma unroll
        for (int i = 0; i < 7; ++i) {
            float g = sgd[i];
            a1.x += g * v[i].x; a1.y += g * v[i].y;
            a1.z += g * v[i].z; a1.w += g * v[i].w;
        }
#pragma unroll
        for (int i = 0; i < 7; ++i) v[i] = xp[i * 784 + (R0 + 28) * 14 + q];
#pragma unroll
        for (int i = 0; i < 7; ++i) {
            float g = sgd[i];
            a2.x += g * v[i].x; a2.y += g * v[i].y;
            a2.z += g * v[i].z; a2.w += g * v[i].w;
        }
        sacc[R0][q] = a1;
        sacc[R0 + 28][q] = a2;
    }
    __syncthreads();

    if (t < 64) {
        int hh = t >> 3, ww = t & 7;
        float s = 0.f;
#pragma unroll
        for (int ih = 0; ih < 7; ++ih) {
            int h = hh * 7 + ih;
            float inner = 0.f;
#pragma unroll
            for (int iw = 0; iw < 7; ++iw) {
                int w = ww * 7 + iw;
                const float* p = reinterpret_cast<const float*>(&sacc[h][w >> 2]);
                inner += p[w & 3] * sgw[w];
            }
            s += inner * sgh[h];
        }
        float yv = s * (1.0f / 343.0f);
        g_y[b][c][dd * 64 + hh * 8 + ww] = yv;
        double sv = yv, sq = (double)yv * yv;
#pragma unroll
        for (int o = 16; o; o >>= 1) {
            sv += __shfl_down_sync(0xffffffffu, sv, o);
            sq += __shfl_down_sync(0xffffffffu, sq, o);
        }
        if ((t & 31) == 0) { pr[t >> 5][0] = sv; pr[t >> 5][1] = sq; }
    }
    __syncthreads();
    if (t == 0) {
        g_part[id][0] = pr[0][0] + pr[1][0];
        g_part[id][1] = pr[0][1] + pr[1][1];
    }
}

// ---------------------------------------------------------------------------
// K4: stats + Gram + channel attention, merged. grid=16 (b,head), 256 threads.
// ---------------------------------------------------------------------------
__global__ void k4_attn(const float* __restrict__ gn, const float* __restrict__ btn,
                        const float* __restrict__ wq, const float* __restrict__ wk,
                        const float* __restrict__ wv) {
    int b = blockIdx.x >> 3;
    int head = blockIdx.x & 7;
    int c0 = head * 16;
    int tid = threadIdx.x;
    __shared__ float yy[16][516];   // padded to kill bank conflicts
    __shared__ double rs[8], rq[8];
    __shared__ float stat[2];
    __shared__ float Syy[16][16];
    __shared__ float Sy[16];

    {
        const float4* src = reinterpret_cast<const float4*>(&g_y[b][c0][0]);
        for (int i = tid; i < 16 * 128; i += 256) {
            int row = i >> 7, s4 = i & 127;
            float4 v = src[row * 128 + s4];
            float* dst = &yy[row][s4 * 4];
            dst[0] = v.x; dst[1] = v.y; dst[2] = v.z; dst[3] = v.w;
        }
    }

    double s = 0.0, q = 0.0;
    for (int i = tid; i < 1024; i += 256) {
        s += g_part[b * 1024 + i][0];
        q += g_part[b * 1024 + i][1];
    }
#pragma unroll
    for (int o = 16; o; o >>= 1) {
        s += __shfl_down_sync(0xffffffffu, s, o);
        q += __shfl_down_sync(0xffffffffu, q, o);
    }
    if ((tid & 31) == 0) { rs[tid >> 5] = s; rq[tid >> 5] = q; }
    __syncthreads();

    {
        int i = tid >> 4, j = tid & 15;
        const float4* ri = reinterpret_cast<const float4*>(&yy[i][0]);
        const float4* rj = reinterpret_cast<const float4*>(&yy[j][0]);
        float a0 = 0.f, a1 = 0.f, a2 = 0.f, a3 = 0.f;
#pragma unroll 4
        for (int s4 = 0; s4 < 128; ++s4) {
            float4 u = ri[s4], w = rj[s4];
            a0 += u.x * w.x; a1 += u.y * w.y;
            a2 += u.z * w.z; a3 += u.w * w.w;
        }
        Syy[i][j] = (a0 + a1) + (a2 + a3);
    }
    if (tid < 16) {
        double a = 0.0;
#pragma unroll
        for (int dd = 0; dd < 8; ++dd) a += g_part[(b * 128 + c0 + tid) * 8 + dd][0];
        Sy[tid] = (float)a;
    }
    if (tid == 0) {
        double S = 0.0, Q = 0.0;
        for (int i = 0; i < 8; ++i) { S += rs[i]; Q += rq[i]; }
        double n = (double)(CC * SLEN);
        double mu = S / n;
        double var = Q / n - mu * mu;
        stat[0] = (float)mu;
        stat[1] = (float)(1.0 / sqrt(var + 1e-5));
    }
    __syncthreads();

    if (tid < 16) {
        double mu = stat[0], rstd = stat[1];
        int i = tid;
        double ai = rstd * (double)gn[c0 + i];
        double bi = (double)btn[c0 + i] - mu * ai;
        double qi = (double)wq[c0 + i] * 0.25;  // includes HD^-0.5
        double sc_[16], vm[16];
        double m = -1e300;
#pragma unroll
        for (int j = 0; j < 16; ++j) {
            double aj = rstd * (double)gn[c0 + j];
            double bj = (double)btn[c0 + j] - mu * aj;
            double G = ai * aj * (double)Syy[i][j] + ai * bj * (double)Sy[i]
                     + bi * aj * (double)Sy[j] + 512.0 * bi * bj;
            sc_[j] = qi * (double)wk[c0 + j] * G;
            vm[j] = (double)wv[c0 + j] * (aj * (double)Sy[j] + 512.0 * bj) * (1.0 / 512.0);
            if (sc_[j] > m) m = sc_[j];
        }
        double sum = 0.0, o = 0.0;
#pragma unroll
        for (int j = 0; j < 16; ++j) {
            double e = exp(sc_[j] - m);
            sum += e;
            o += e * vm[j];
        }
        o /= sum;
        g_ca[b][c0 + i] = (float)(1.0 / (1.0 + exp(-o)));
    }
}

// ---------------------------------------------------------------------------
// K5: out = x * gd*gh*gw*ca. grid = bc*8+ch (2048), blockDim 416, forward
// order, plain loads/stores (R5 hints reverted), 2x batched 7-deep MLP.
// ---------------------------------------------------------------------------
__global__ void __launch_bounds__(416, 2) k5_gate_out(const float* __restrict__ x,
                                                      float* __restrict__ out) {
    int id = blockIdx.x;
    int ch = id & 7;
    int bc = id >> 3;
    int b = bc >> 7, c = bc & 127;
    const float4* xp = reinterpret_cast<const float4*>(x + (size_t)bc * SP);
    float4* op = reinterpret_cast<float4*>(out + (size_t)bc * SP);

    __shared__ float srs[392];
    __shared__ float4 sgw4[14];

    int t = threadIdx.x;
    bool act = t < 392;
    if (act) {
        int dl = t / 56, h = t % 56;
        srs[t] = g_gate[0][b][c][ch * 7 + dl] * g_gate[1][b][c][h] * g_ca[b][c];
    }
    if (t < 14) {
        sgw4[t] = reinterpret_cast<const float4*>(&g_gate[2][b][c][0])[t];
    }
    __syncthreads();

    if (act) {
        int q = t % 14, R0 = t / 14;
        float4 gw = sgw4[q];
        int base = ch * 5488 + R0 * 14 + q;
        float4 v[7];
#pragma unroll
        for (int half = 0; half < 2; ++half) {
            int m0 = half * 7;
#pragma unroll
            for (int m = 0; m < 7; ++m) v[m] = xp[base + (m0 + m) * 392];
#pragma unroll
            for (int m = 0; m < 7; ++m) {
                float sc = srs[R0 + 28 * (m0 + m)];
                float4 u = v[m];
                u.x *= sc * gw.x;
                u.y *= sc * gw.y;
                u.z *= sc * gw.z;
                u.w *= sc * gw.w;
                op[base + (m0 + m) * 392] = u;
            }
        }
    }
}

// ---------------------------------------------------------------------------
extern "C" void kernel_launch(void* const* d_in, const int* in_sizes, int n_in,
                              void* d_out, int out_size) {
    const float* x = (const float*)d_in[0];
    float* out = (float*)d_out;

#define GATE_ARGS \
    (const float*)d_in[1], (const float*)d_in[2],   \
    (const float*)d_in[3], (const float*)d_in[4],   \
    (const float*)d_in[5], (const float*)d_in[6],   \
    (const float*)d_in[7], (const float*)d_in[8],   \
    (const float*)d_in[9], (const float*)d_in[10],  \
    (const float*)d_in[11], (const float*)d_in[12], \
    (const float*)d_in[13], (const float*)d_in[14]

    k1_axis_means<<<BB * CC * 8, 416>>>(x);
    k2_gates<<<16, 256>>>(0, GATE_ARGS);   // axes d, h
    k2_gates<<<8, 256>>>(2, GATE_ARGS);    // axis w
    k3_pool<<<BB * CC * 8, 416>>>(x);      // 4th launch -> profiled by ncu
    k4_attn<<<BB * 8, 256>>>(
        (const float*)d_in[15], (const float*)d_in[16],
        (const float*)d_in[17], (const float*)d_in[18],
        (const float*)d_in[19]);
    k5_gate_out<<<BB * CC * 8, 416>>>(x, out);
#undef GATE_ARGS
}

// round 7
// speedup vs baseline: 1.2884x; 1.0237x over previous
#include <cuda_runtime.h>
#include <math.h>

#define BB 2
#define CC 128
#define LL 56
#define PL 3136      // 56*56
#define SP 175616    // 56^3
#define SLEN 512     // 8*8*8 pooled spatial

// Scratch (static device globals; no allocation)
__device__ __align__(16) float g_sax0[BB][CC][LL];     // d-axis means (complete)
__device__ __align__(16) float g_shp[BB * CC][4][LL];  // h-axis partials (4 chunks)
__device__ __align__(16) float g_swp[BB * CC][4][LL];  // w-axis partials (4 chunks)
__device__ __align__(16) float g_gate[3][BB][CC][LL];  // sigmoid gates
__device__ __align__(16) float g_y[BB][CC][SLEN];      // pooled tensor
__device__ double g_part[BB * CC * 8][2];              // per-(bc,dd) (sum,sumsq)
__device__ float g_ca[BB][CC];                         // channel attention

__device__ __forceinline__ float hsum4(float4 v) {
    return (v.x + v.y) + (v.z + v.w);
}

// ---------------------------------------------------------------------------
// K1: axis-mean partials. grid = bc*4+chunk (1024 blocks), 14 planes/block,
// blockDim 416 (act t<392). 4 batched load groups, no mid-kernel syncs;
// shuffle reduces issued after the next batch's loads.
// ---------------------------------------------------------------------------
__global__ void __launch_bounds__(416, 2) k1_axis_means(const float* __restrict__ x) {
    int id = blockIdx.x;
    int chunk = id & 3;
    int bc = id >> 2;
    const float4* xp = reinterpret_cast<const float4*>(x + (size_t)bc * SP)
                     + (size_t)chunk * 14 * 784;

    __shared__ float sdp[13][14];     // warp x plane partials
    __shared__ float shq[56][14];     // per-(h,q) sums
    __shared__ float4 swq[28][14];    // per-(R0,q) float4 sums

    int t = threadIdx.x;
    bool act = t < 392;
    int q = t % 14, R0 = t / 14;
    int wid = t >> 5, lane = t & 31;

    float4 v[7];
    float pdA[7], pdB[7];
    float4 ah1 = {0, 0, 0, 0}, ah2 = {0, 0, 0, 0}, aw = {0, 0, 0, 0};
    float4 z = {0, 0, 0, 0};

    // batch A: planes 0-6, row R0
#pragma unroll
    for (int i = 0; i < 7; ++i) v[i] = act ? xp[i * 784 + R0 * 14 + q] : z;
#pragma unroll
    for (int i = 0; i < 7; ++i) {
        pdA[i] = hsum4(v[i]);
        ah1.x += v[i].x; ah1.y += v[i].y; ah1.z += v[i].z; ah1.w += v[i].w;
        aw.x += v[i].x; aw.y += v[i].y; aw.z += v[i].z; aw.w += v[i].w;
    }
    // batch B: planes 0-6, row R0+28
#pragma unroll
    for (int i = 0; i < 7; ++i) v[i] = act ? xp[i * 784 + (R0 + 28) * 14 + q] : z;
#pragma unroll
    for (int i = 0; i < 7; ++i) {
        pdA[i] += hsum4(v[i]);
        ah2.x += v[i].x; ah2.y += v[i].y; ah2.z += v[i].z; ah2.w += v[i].w;
        aw.x += v[i].x; aw.y += v[i].y; aw.z += v[i].z; aw.w += v[i].w;
    }
    // batch C loads first (cover pdA shuffles), planes 7-13 row R0
#pragma unroll
    for (int i = 0; i < 7; ++i) v[i] = act ? xp[(7 + i) * 784 + R0 * 14 + q] : z;
#pragma unroll
    for (int i = 0; i < 7; ++i) {
        float s = pdA[i];
#pragma unroll
        for (int o = 16; o; o >>= 1) s += __shfl_down_sync(0xffffffffu, s, o);
        if (lane == 0) sdp[wid][i] = s;
    }
#pragma unroll
    for (int i = 0; i < 7; ++i) {
        pdB[i] = hsum4(v[i]);
        ah1.x += v[i].x; ah1.y += v[i].y; ah1.z += v[i].z; ah1.w += v[i].w;
        aw.x += v[i].x; aw.y += v[i].y; aw.z += v[i].z; aw.w += v[i].w;
    }
    // batch D: planes 7-13, row R0+28
#pragma unroll
    for (int i = 0; i < 7; ++i) v[i] = act ? xp[(7 + i) * 784 + (R0 + 28) * 14 + q] : z;
#pragma unroll
    for (int i = 0; i < 7; ++i) {
        pdB[i] += hsum4(v[i]);
        ah2.x += v[i].x; ah2.y += v[i].y; ah2.z += v[i].z; ah2.w += v[i].w;
        aw.x += v[i].x; aw.y += v[i].y; aw.z += v[i].z; aw.w += v[i].w;
    }
#pragma unroll
    for (int i = 0; i < 7; ++i) {
        float s = pdB[i];
#pragma unroll
        for (int o = 16; o; o >>= 1) s += __shfl_down_sync(0xffffffffu, s, o);
        if (lane == 0) sdp[wid][7 + i] = s;
    }
    if (act) {
        shq[R0][q] = hsum4(ah1);
        shq[R0 + 28][q] = hsum4(ah2);
        swq[R0][q] = aw;
    }
    __syncthreads();

    int b = bc >> 7, c = bc & 127;
    if (t < 14) {
        float s = 0.f;
#pragma unroll
        for (int w = 0; w < 13; ++w) s += sdp[w][t];
        g_sax0[b][c][chunk * 14 + t] = s * (1.0f / (float)PL);
    } else if (t >= 64 && t < 64 + LL) {
        int h = t - 64;
        float s = 0.f;
#pragma unroll
        for (int j = 0; j < 14; ++j) s += shq[h][j];
        g_shp[bc][chunk][h] = s;
    } else if (t >= 128 && t < 128 + LL) {
        int w = t - 128;
        int qq = w >> 2, comp = w & 3;
        float s = 0.f;
#pragma unroll
        for (int r = 0; r < 28; ++r) {
            const float* p = reinterpret_cast<const float*>(&swq[r][qq]);
            s += p[comp];
        }
        g_swp[bc][chunk][w] = s;
    }
}

// ---------------------------------------------------------------------------
// K2: combine partials + depthwise conv + GroupNorm(4) + sigmoid.
// Launched twice: grid 16 (axes 0,1) and grid 8 (axis 2, axis_base=2).
// ---------------------------------------------------------------------------
__global__ void k2_gates(int axis_base,
                         const float* __restrict__ wl, const float* __restrict__ bl,
                         const float* __restrict__ ws, const float* __restrict__ bs,
                         const float* __restrict__ wm, const float* __restrict__ bm,
                         const float* __restrict__ wg, const float* __restrict__ bg,
                         const float* __restrict__ gd, const float* __restrict__ btd,
                         const float* __restrict__ gh, const float* __restrict__ bth,
                         const float* __restrict__ gw, const float* __restrict__ btw) {
    int idx = blockIdx.x;
    int axis = axis_base + (idx >> 3);
    int b = (idx >> 2) & 1;
    int g = idx & 3;
    const int ksz[4] = {3, 5, 7, 9};
    const float* wptr[4] = {wl, ws, wm, wg};
    const float* bptr[4] = {bl, bs, bm, bg};
    const float* gam[3] = {gd, gh, gw};
    const float* bet[3] = {btd, bth, btw};
    int k = ksz[g], half = k >> 1;

    __shared__ float s_in[32][LL];
    __shared__ float s_out[32][LL];
    __shared__ float s_w[32 * 9];
    __shared__ float s_b[32];
    __shared__ float red[2];
    __shared__ float rs[8], rq[8];

    int tid = threadIdx.x;
    for (int i = tid; i < 32 * LL; i += 256) {
        int cc = i / LL, l = i % LL;
        int c = g * 32 + cc;
        float v;
        if (axis == 0) {
            v = g_sax0[b][c][l];
        } else {
            int bcc = b * 128 + c;
            const float(*pp)[4][LL] = (axis == 1) ? g_shp : g_swp;
            v = (pp[bcc][0][l] + pp[bcc][1][l] + pp[bcc][2][l] + pp[bcc][3][l])
                * (1.0f / (float)PL);
        }
        s_in[cc][l] = v;
    }
    for (int i = tid; i < 32 * k; i += 256) s_w[i] = wptr[g][i];
    if (tid < 32) s_b[tid] = bptr[g][tid];
    __syncthreads();

    float lsum = 0.f, lsq = 0.f;
    for (int i = tid; i < 32 * LL; i += 256) {
        int cc = i / LL, l = i % LL;
        float acc = s_b[cc];
        for (int j = 0; j < k; ++j) {
            int p = l + j - half;
            if (p >= 0 && p < LL) acc += s_w[cc * k + j] * s_in[cc][p];
        }
        s_out[cc][l] = acc;
        lsum += acc;
        lsq += acc * acc;
    }
#pragma unroll
    for (int o = 16; o; o >>= 1) {
        lsum += __shfl_down_sync(0xffffffffu, lsum, o);
        lsq  += __shfl_down_sync(0xffffffffu, lsq, o);
    }
    if ((tid & 31) == 0) { rs[tid >> 5] = lsum; rq[tid >> 5] = lsq; }
    __syncthreads();
    if (tid == 0) {
        float S = 0.f, Q = 0.f;
        for (int i = 0; i < 8; ++i) { S += rs[i]; Q += rq[i]; }
        float n = 32.f * LL;
        float mu = S / n;
        float var = Q / n - mu * mu;
        red[0] = mu;
        red[1] = rsqrtf(var + 1e-5f);
    }
    __syncthreads();
    float mu = red[0], rstd = red[1];
    for (int i = tid; i < 32 * LL; i += 256) {
        int cc = i / LL, l = i % LL;
        int c = g * 32 + cc;
        float v = (s_out[cc][l] - mu) * rstd * gam[axis][c] + bet[axis][c];
        g_gate[axis][b][c][l] = 1.f / (1.f + expf(-v));
    }
}

// ---------------------------------------------------------------------------
// K3: pool gated x into y, pipelined 2 units/block. grid = bc*4+pair (1024),
// blockDim 416. Unit = (bc, dd); block handles dd = pair*2, pair*2+1.
// Unit-1's first loads issue before unit-0's reduce -> tail hidden.
// ---------------------------------------------------------------------------
__global__ void __launch_bounds__(416, 2) k3_pool(const float* __restrict__ x) {
    int id = blockIdx.x;
    int pair = id & 3;
    int bc = id >> 2;
    int b = bc >> 7, c = bc & 127;
    const float4* xp = reinterpret_cast<const float4*>(x + (size_t)bc * SP)
                     + (size_t)pair * 14 * 784;

    __shared__ float sgd[14], sgh[LL], sgw[LL];
    __shared__ float4 sacc[56][14];
    __shared__ double pr[2][2];

    int t = threadIdx.x;
    bool act = t < 392;
    int q = t % 14, R0 = t / 14;

    if (t < LL) { sgh[t] = g_gate[1][b][c][t]; sgw[t] = g_gate[2][b][c][t]; }
    if (t >= 64 && t < 78) sgd[t - 64] = g_gate[0][b][c][pair * 14 + (t - 64)];
    __syncthreads();

    float4 v[7];
    // ---- unit 0 (planes 0-6 of this 14-plane window) ----
    if (act) {
        float4 a1 = {0, 0, 0, 0}, a2 = {0, 0, 0, 0};
#pragma unroll
        for (int i = 0; i < 7; ++i) v[i] = xp[i * 784 + R0 * 14 + q];
#pragma unroll
        for (int i = 0; i < 7; ++i) {
            float g = sgd[i];
            a1.x += g * v[i].x; a1.y += g * v[i].y;
            a1.z += g * v[i].z; a1.w += g * v[i].w;
        }
#pragma unroll
        for (int i = 0; i < 7; ++i) v[i] = xp[i * 784 + (R0 + 28) * 14 + q];
#pragma unroll
        for (int i = 0; i < 7; ++i) {
            float g = sgd[i];
            a2.x += g * v[i].x; a2.y += g * v[i].y;
            a2.z += g * v[i].z; a2.w += g * v[i].w;
        }
        sacc[R0][q] = a1;
        sacc[R0 + 28][q] = a2;
        // prefetch unit 1 batch 1 (in flight during unit-0 reduce)
#pragma unroll
        for (int i = 0; i < 7; ++i) v[i] = xp[(7 + i) * 784 + R0 * 14 + q];
    }
    __syncthreads();

    // reduce unit 0
    if (t < 64) {
        int hh = t >> 3, ww = t & 7;
        float s = 0.f;
#pragma unroll
        for (int ih = 0; ih < 7; ++ih) {
            int h = hh * 7 + ih;
            float inner = 0.f;
#pragma unroll
            for (int iw = 0; iw < 7; ++iw) {
                int w = ww * 7 + iw;
                const float* p = reinterpret_cast<const float*>(&sacc[h][w >> 2]);
                inner += p[w & 3] * sgw[w];
            }
            s += inner * sgh[h];
        }
        float yv = s * (1.0f / 343.0f);
        g_y[b][c][(pair * 2) * 64 + hh * 8 + ww] = yv;
        double sv = yv, sq = (double)yv * yv;
#pragma unroll
        for (int o = 16; o; o >>= 1) {
            sv += __shfl_down_sync(0xffffffffu, sv, o);
            sq += __shfl_down_sync(0xffffffffu, sq, o);
        }
        if ((t & 31) == 0) { pr[t >> 5][0] = sv; pr[t >> 5][1] = sq; }
    }
    __syncthreads();
    if (t == 0) {
        g_part[bc * 8 + pair * 2][0] = pr[0][0] + pr[1][0];
        g_part[bc * 8 + pair * 2][1] = pr[0][1] + pr[1][1];
    }

    // ---- unit 1 (planes 7-13) ----
    if (act) {
        float4 a1 = {0, 0, 0, 0}, a2 = {0, 0, 0, 0};
#pragma unroll
        for (int i = 0; i < 7; ++i) {
            float g = sgd[7 + i];
            a1.x += g * v[i].x; a1.y += g * v[i].y;
            a1.z += g * v[i].z; a1.w += g * v[i].w;
        }
#pragma unroll
        for (int i = 0; i < 7; ++i) v[i] = xp[(7 + i) * 784 + (R0 + 28) * 14 + q];
#pragma unroll
        for (int i = 0; i < 7; ++i) {
            float g = sgd[7 + i];
            a2.x += g * v[i].x; a2.y += g * v[i].y;
            a2.z += g * v[i].z; a2.w += g * v[i].w;
        }
        sacc[R0][q] = a1;
        sacc[R0 + 28][q] = a2;
    }
    __syncthreads();

    if (t < 64) {
        int hh = t >> 3, ww = t & 7;
        float s = 0.f;
#pragma unroll
        for (int ih = 0; ih < 7; ++ih) {
            int h = hh * 7 + ih;
            float inner = 0.f;
#pragma unroll
            for (int iw = 0; iw < 7; ++iw) {
                int w = ww * 7 + iw;
                const float* p = reinterpret_cast<const float*>(&sacc[h][w >> 2]);
                inner += p[w & 3] * sgw[w];
            }
            s += inner * sgh[h];
        }
        float yv = s * (1.0f / 343.0f);
        g_y[b][c][(pair * 2 + 1) * 64 + hh * 8 + ww] = yv;
        double sv = yv, sq = (double)yv * yv;
#pragma unroll
        for (int o = 16; o; o >>= 1) {
            sv += __shfl_down_sync(0xffffffffu, sv, o);
            sq += __shfl_down_sync(0xffffffffu, sq, o);
        }
        if ((t & 31) == 0) { pr[t >> 5][0] = sv; pr[t >> 5][1] = sq; }
    }
    __syncthreads();
    if (t == 0) {
        g_part[bc * 8 + pair * 2 + 1][0] = pr[0][0] + pr[1][0];
        g_part[bc * 8 + pair * 2 + 1][1] = pr[0][1] + pr[1][1];
    }
}

// ---------------------------------------------------------------------------
// K4: stats + Gram + channel attention, merged. grid=16 (b,head), 256 threads.
// ---------------------------------------------------------------------------
__global__ void k4_attn(const float* __restrict__ gn, const float* __restrict__ btn,
                        const float* __restrict__ wq, const float* __restrict__ wk,
                        const float* __restrict__ wv) {
    int b = blockIdx.x >> 3;
    int head = blockIdx.x & 7;
    int c0 = head * 16;
    int tid = threadIdx.x;
    __shared__ float yy[16][516];
    __shared__ double rs[8], rq[8];
    __shared__ float stat[2];
    __shared__ float Syy[16][16];
    __shared__ float Sy[16];

    {
        const float4* src = reinterpret_cast<const float4*>(&g_y[b][c0][0]);
        for (int i = tid; i < 16 * 128; i += 256) {
            int row = i >> 7, s4 = i & 127;
            float4 v = src[row * 128 + s4];
            float* dst = &yy[row][s4 * 4];
            dst[0] = v.x; dst[1] = v.y; dst[2] = v.z; dst[3] = v.w;
        }
    }

    double s = 0.0, q = 0.0;
    for (int i = tid; i < 1024; i += 256) {
        s += g_part[b * 1024 + i][0];
        q += g_part[b * 1024 + i][1];
    }
#pragma unroll
    for (int o = 16; o; o >>= 1) {
        s += __shfl_down_sync(0xffffffffu, s, o);
        q += __shfl_down_sync(0xffffffffu, q, o);
    }
    if ((tid & 31) == 0) { rs[tid >> 5] = s; rq[tid >> 5] = q; }
    __syncthreads();

    {
        int i = tid >> 4, j = tid & 15;
        const float4* ri = reinterpret_cast<const float4*>(&yy[i][0]);
        const float4* rj = reinterpret_cast<const float4*>(&yy[j][0]);
        float a0 = 0.f, a1 = 0.f, a2 = 0.f, a3 = 0.f;
#pragma unroll 4
        for (int s4 = 0; s4 < 128; ++s4) {
            float4 u = ri[s4], w = rj[s4];
            a0 += u.x * w.x; a1 += u.y * w.y;
            a2 += u.z * w.z; a3 += u.w * w.w;
        }
        Syy[i][j] = (a0 + a1) + (a2 + a3);
    }
    if (tid < 16) {
        double a = 0.0;
#pragma unroll
        for (int dd = 0; dd < 8; ++dd) a += g_part[(b * 128 + c0 + tid) * 8 + dd][0];
        Sy[tid] = (float)a;
    }
    if (tid == 0) {
        double S = 0.0, Q = 0.0;
        for (int i = 0; i < 8; ++i) { S += rs[i]; Q += rq[i]; }
        double n = (double)(CC * SLEN);
        double mu = S / n;
        double var = Q / n - mu * mu;
        stat[0] = (float)mu;
        stat[1] = (float)(1.0 / sqrt(var + 1e-5));
    }
    __syncthreads();

    if (tid < 16) {
        double mu = stat[0], rstd = stat[1];
        int i = tid;
        double ai = rstd * (double)gn[c0 + i];
        double bi = (double)btn[c0 + i] - mu * ai;
        double qi = (double)wq[c0 + i] * 0.25;  // includes HD^-0.5
        double sc_[16], vm[16];
        double m = -1e300;
#pragma unroll
        for (int j = 0; j < 16; ++j) {
            double aj = rstd * (double)gn[c0 + j];
            double bj = (double)btn[c0 + j] - mu * aj;
            double G = ai * aj * (double)Syy[i][j] + ai * bj * (double)Sy[i]
                     + bi * aj * (double)Sy[j] + 512.0 * bi * bj;
            sc_[j] = qi * (double)wk[c0 + j] * G;
            vm[j] = (double)wv[c0 + j] * (aj * (double)Sy[j] + 512.0 * bj) * (1.0 / 512.0);
            if (sc_[j] > m) m = sc_[j];
        }
        double sum = 0.0, o = 0.0;
#pragma unroll
        for (int j = 0; j < 16; ++j) {
            double e = exp(sc_[j] - m);
            sum += e;
            o += e * vm[j];
        }
        o /= sum;
        g_ca[b][c0 + i] = (float)(1.0 / (1.0 + exp(-o)));
    }
}

// ---------------------------------------------------------------------------
// K5: out = x * gd*gh*gw*ca. grid = bc*8+ch (2048), blockDim 416,
// 2x batched 7-deep MLP, no sync tails.
// ---------------------------------------------------------------------------
__global__ void __launch_bounds__(416, 2) k5_gate_out(const float* __restrict__ x,
                                                      float* __restrict__ out) {
    int id = blockIdx.x;
    int ch = id & 7;
    int bc = id >> 3;
    int b = bc >> 7, c = bc & 127;
    const float4* xp = reinterpret_cast<const float4*>(x + (size_t)bc * SP);
    float4* op = reinterpret_cast<float4*>(out + (size_t)bc * SP);

    __shared__ float srs[392];
    __shared__ float4 sgw4[14];

    int t = threadIdx.x;
    bool act = t < 392;
    if (act) {
        int dl = t / 56, h = t % 56;
        srs[t] = g_gate[0][b][c][ch * 7 + dl] * g_gate[1][b][c][h] * g_ca[b][c];
    }
    if (t < 14) {
        sgw4[t] = reinterpret_cast<const float4*>(&g_gate[2][b][c][0])[t];
    }
    __syncthreads();

    if (act) {
        int q = t % 14, R0 = t / 14;
        float4 gw = sgw4[q];
        int base = ch * 5488 + R0 * 14 + q;
        float4 v[7];
#pragma unroll
        for (int half = 0; half < 2; ++half) {
            int m0 = half * 7;
#pragma unroll
            for (int m = 0; m < 7; ++m) v[m] = xp[base + (m0 + m) * 392];
#pragma unroll
            for (int m = 0; m < 7; ++m) {
                float sc = srs[R0 + 28 * (m0 + m)];
                float4 u = v[m];
                u.x *= sc * gw.x;
                u.y *= sc * gw.y;
                u.z *= sc * gw.z;
                u.w *= sc * gw.w;
                op[base + (m0 + m) * 392] = u;
            }
        }
    }
}

// ---------------------------------------------------------------------------
extern "C" void kernel_launch(void* const* d_in, const int* in_sizes, int n_in,
                              void* d_out, int out_size) {
    const float* x = (const float*)d_in[0];
    float* out = (float*)d_out;

#define GATE_ARGS \
    (const float*)d_in[1], (const float*)d_in[2],   \
    (const float*)d_in[3], (const float*)d_in[4],   \
    (const float*)d_in[5], (const float*)d_in[6],   \
    (const float*)d_in[7], (const float*)d_in[8],   \
    (const float*)d_in[9], (const float*)d_in[10],  \
    (const float*)d_in[11], (const float*)d_in[12], \
    (const float*)d_in[13], (const float*)d_in[14]

    k1_axis_means<<<BB * CC * 4, 416>>>(x);
    k2_gates<<<16, 256>>>(0, GATE_ARGS);   // axes d, h
    k2_gates<<<8, 256>>>(2, GATE_ARGS);    // axis w
    k3_pool<<<BB * CC * 4, 416>>>(x);      // 4th launch -> profiled by ncu
    k4_attn<<<BB * 8, 256>>>(
        (const float*)d_in[15], (const float*)d_in[16],
        (const float*)d_in[17], (const float*)d_in[18],
        (const float*)d_in[19]);
    k5_gate_out<<<BB * CC * 8, 416>>>(x, out);
#undef GATE_ARGS
}